// round 13
// baseline (speedup 1.0000x reference)
#include <cuda_runtime.h>
#include <cuda_bf16.h>
#include <cstdint>
#include <math.h>

// ---------------------------------------------------------------------------
// RWKV6Attention: B=4, T=2048, HID=1024, NH=4, KD=512, VD=1024, DK=128, DV=256
// Round 13: scan v3 -- warp-local (shfl) output reduction, quad-buffered
// cp.async chunks (ONE barrier per 8 steps), 4-way op accumulators.
// GEMMs unchanged from Round 12.
// ---------------------------------------------------------------------------

#define BB 4
#define TT 2048
#define HID 1024
#define NH 4
#define KD 512
#define VD 1024
#define DK 128
#define DV 256
#define MM (BB*TT)   // 8192

// ------------------------- scratch (device globals) ------------------------
__device__ float g_A0  [(size_t)MM*HID];
__device__ float g_xp  [(size_t)MM*160];
__device__ float g_A5  [(size_t)5*MM*HID];   // slot-major: r,w,k,v,g
__device__ float g_rk  [(size_t)2*MM*KD];    // slot 0: r, slot 1: k
__device__ float g_dec [(size_t)MM*KD];
__device__ float g_wt4 [(size_t)4*MM*64];
__device__ float g_wt  [(size_t)MM*64];
__device__ float g_vg  [(size_t)2*MM*VD];    // slot 0: v, slot 1: g
__device__ float g_c   [(size_t)BB*NH*TT];
__device__ float g_o   [(size_t)MM*VD];
__device__ float g_gate[(size_t)MM*VD];

// tf32-rounded weights
__device__ float g_Wx0r[160*HID];
__device__ float g_Wrk [(size_t)2*KD*HID];
__device__ float g_Wvg [(size_t)2*VD*HID];
__device__ float g_Wor [HID*VD];
__device__ float g_Wx2r[HID*160];

// ------------------------- helpers -----------------------------------------
__device__ __forceinline__ uint32_t smem_u32(const void* p) {
    uint32_t a;
    asm("{ .reg .u64 t; cvta.to.shared.u64 t, %1; cvt.u32.u64 %0, t; }" : "=r"(a) : "l"(p));
    return a;
}
__device__ __forceinline__ float tf32r(float x) {
    uint32_t u;
    asm("cvt.rna.tf32.f32 %0, %1;" : "=r"(u) : "f"(x));
    return __uint_as_float(u);
}
__device__ __forceinline__ void cp16(uint32_t dst, const void* src, bool pred) {
    asm volatile("cp.async.ca.shared.global [%0], [%1], 16, %2;"
                 :: "r"(dst), "l"(src), "r"(pred ? 16u : 0u));
}
__device__ __forceinline__ void mma1688(float* c, const uint32_t* a, const uint32_t* b) {
    asm volatile(
        "mma.sync.aligned.m16n8k8.row.col.f32.tf32.tf32.f32 "
        "{%0,%1,%2,%3}, {%4,%5,%6,%7}, {%8,%9}, {%0,%1,%2,%3};"
        : "+f"(c[0]), "+f"(c[1]), "+f"(c[2]), "+f"(c[3])
        : "r"(a[0]), "r"(a[1]), "r"(a[2]), "r"(a[3]), "r"(b[0]), "r"(b[1]));
}

// ------------------------- tf32 mma.sync GEMM -------------------------------
enum { EPI_NONE = 0, EPI_TANH = 1, EPI_DECAY = 2, EPI_LERP = 3 };

#define SMPAD 36
#define SMBUF (128*SMPAD)

template <int EPI>
__global__ void __launch_bounds__(256) gemm_mma(
    const float* __restrict__ A, const float* __restrict__ W,
    const float* __restrict__ bias, float* __restrict__ C,
    int N, int K, int lda, int ldw, int ldc,
    size_t zsA, size_t zsW, size_t zsB, size_t zsC,
    const float* __restrict__ X)
{
    extern __shared__ float sm[];
    float* sA = sm;                    // [2][SMBUF]
    float* sB = sm + 2 * SMBUF;        // [2][SMBUF]

    const int z = blockIdx.z;
    A += (size_t)z * zsA;
    W += (size_t)z * zsW;
    if (bias) bias += (size_t)z * zsB;
    C += (size_t)z * zsC;

    const int tid = threadIdx.x;
    const int lane = tid & 31;
    const int wid = tid >> 5;
    const int bm = blockIdx.y * 128;
    const int bn = blockIdx.x * 128;
    const int wm = (wid >> 2) * 64;
    const int wn = (wid & 3) * 32;
    const int grp = lane >> 2;
    const int tg = lane & 3;

    float acc[4][4][4];
#pragma unroll
    for (int i = 0; i < 4; i++)
#pragma unroll
        for (int j = 0; j < 4; j++)
#pragma unroll
            for (int q = 0; q < 4; q++) acc[i][j][q] = 0.f;

    auto load_tiles = [&](int ks, int buf) {
#pragma unroll
        for (int i = 0; i < 4; i++) {
            int idx = i * 256 + tid;
            int row = idx >> 3, c4 = idx & 7;
            const float* srcA = A + (size_t)(bm + row) * lda + ks * 32 + c4 * 4;
            cp16(smem_u32(sA + buf * SMBUF + row * SMPAD + c4 * 4), srcA, true);
            int gn = bn + row;
            bool ok = gn < N;
            const float* srcB = W + (size_t)(ok ? gn : 0) * ldw + ks * 32 + c4 * 4;
            cp16(smem_u32(sB + buf * SMBUF + row * SMPAD + c4 * 4), srcB, ok);
        }
        asm volatile("cp.async.commit_group;" ::: "memory");
    };

    const int S = K >> 5;
    load_tiles(0, 0);

    for (int s = 0; s < S; s++) {
        const int buf = s & 1;
        if (s + 1 < S) {
            load_tiles(s + 1, buf ^ 1);
            asm volatile("cp.async.wait_group 1;" ::: "memory");
        } else {
            asm volatile("cp.async.wait_group 0;" ::: "memory");
        }
        __syncthreads();

        const float* pA = sA + buf * SMBUF + wm * SMPAD;
        const float* pB = sB + buf * SMBUF + wn * SMPAD;
#pragma unroll
        for (int kk = 0; kk < 4; kk++) {
            const int kb = kk * 8;
            uint32_t a[4][4], b[4][2];
#pragma unroll
            for (int mt = 0; mt < 4; mt++) {
                int r0 = mt * 16 + grp;
                a[mt][0] = __float_as_uint(pA[r0 * SMPAD + kb + tg]);
                a[mt][1] = __float_as_uint(pA[(r0 + 8) * SMPAD + kb + tg]);
                a[mt][2] = __float_as_uint(pA[r0 * SMPAD + kb + tg + 4]);
                a[mt][3] = __float_as_uint(pA[(r0 + 8) * SMPAD + kb + tg + 4]);
            }
#pragma unroll
            for (int nt = 0; nt < 4; nt++) {
                int c0 = nt * 8 + grp;
                b[nt][0] = __float_as_uint(pB[c0 * SMPAD + kb + tg]);
                b[nt][1] = __float_as_uint(pB[c0 * SMPAD + kb + tg + 4]);
            }
#pragma unroll
            for (int mt = 0; mt < 4; mt++)
#pragma unroll
                for (int nt = 0; nt < 4; nt++)
                    mma1688(acc[mt][nt], a[mt], b[nt]);
        }
        __syncthreads();
    }

    // epilogue
#pragma unroll
    for (int mt = 0; mt < 4; mt++) {
#pragma unroll
        for (int nt = 0; nt < 4; nt++) {
            int col = bn + wn + nt * 8 + tg * 2;
            if (col >= N) continue;
            float bv0 = bias ? bias[col] : 0.f;
            float bv1 = bias ? bias[col + 1] : 0.f;
#pragma unroll
            for (int half = 0; half < 2; half++) {
                int row = bm + wm + mt * 16 + grp + half * 8;
                float v0 = acc[mt][nt][half * 2 + 0] + bv0;
                float v1 = acc[mt][nt][half * 2 + 1] + bv1;
                if (EPI == EPI_TANH)  { v0 = tf32r(tanhf(v0)); v1 = tf32r(tanhf(v1)); }
                if (EPI == EPI_DECAY) { v0 = expf(-expf(v0)); v1 = expf(-expf(v1)); }
                if (EPI == EPI_LERP) {
                    size_t xi = (size_t)row * HID + col;
                    float2 xv = *(const float2*)&X[xi];
                    int t = row & (TT - 1);
                    float2 sh = (t == 0) ? make_float2(0.f, 0.f)
                                         : *(const float2*)&X[xi - HID];
                    v0 = xv.x + (sh.x - xv.x) * v0;
                    v1 = xv.y + (sh.y - xv.y) * v1;
                    if (z != 1) { v0 = tf32r(v0); v1 = tf32r(v1); }  // w slot stays fp32
                }
                *(float2*)&C[(size_t)row * ldc + col] = make_float2(v0, v1);
            }
        }
    }
}

// ------------------------- fp32 SGEMM (w path) ------------------------------
template <int EPI>
__global__ void sgemm_nt(const float* __restrict__ A, const float* __restrict__ W,
                         const float* __restrict__ bias, float* __restrict__ C,
                         int M, int N, int K, int lda, int ldw, int ldc,
                         int zsA, int zsW, int zsC) {
    __shared__ float As[8][128];
    __shared__ float Ws[8][128];
    const int z = blockIdx.z;
    A += (size_t)z * zsA;
    W += (size_t)z * zsW;
    C += (size_t)z * zsC;

    const int tid = threadIdx.x;
    const int bm = blockIdx.y * 128;
    const int bn = blockIdx.x * 128;
    const int lr = tid >> 1;
    const int lc = (tid & 1) << 2;
    const int tx = tid & 15;
    const int ty = tid >> 4;

    float acc[8][8];
#pragma unroll
    for (int i = 0; i < 8; i++)
#pragma unroll
        for (int j = 0; j < 8; j++) acc[i][j] = 0.f;

    const bool wok = (bn + lr) < N;
    const float* Aptr = A + (size_t)(bm + lr) * lda + lc;
    const float* Wptr = W + (size_t)(wok ? (bn + lr) : 0) * ldw + lc;

    for (int k0 = 0; k0 < K; k0 += 8) {
        float4 av = *(const float4*)(Aptr + k0);
        float4 wv = wok ? *(const float4*)(Wptr + k0) : make_float4(0.f, 0.f, 0.f, 0.f);
        As[lc + 0][lr] = av.x; As[lc + 1][lr] = av.y; As[lc + 2][lr] = av.z; As[lc + 3][lr] = av.w;
        Ws[lc + 0][lr] = wv.x; Ws[lc + 1][lr] = wv.y; Ws[lc + 2][lr] = wv.z; Ws[lc + 3][lr] = wv.w;
        __syncthreads();
#pragma unroll
        for (int kk = 0; kk < 8; kk++) {
            float a[8], b[8];
            *(float4*)&a[0] = *(const float4*)&As[kk][ty * 8];
            *(float4*)&a[4] = *(const float4*)&As[kk][ty * 8 + 4];
            *(float4*)&b[0] = *(const float4*)&Ws[kk][tx * 8];
            *(float4*)&b[4] = *(const float4*)&Ws[kk][tx * 8 + 4];
#pragma unroll
            for (int i = 0; i < 8; i++)
#pragma unroll
                for (int j = 0; j < 8; j++) acc[i][j] = fmaf(a[i], b[j], acc[i][j]);
        }
        __syncthreads();
    }

#pragma unroll
    for (int i = 0; i < 8; i++) {
        int row = bm + ty * 8 + i;
#pragma unroll
        for (int j = 0; j < 8; j++) {
            int col = bn + tx * 8 + j;
            if (col < N) {
                float val = acc[i][j];
                if (bias) val += bias[col];
                if (EPI == EPI_TANH)  val = tanhf(val);
                if (EPI == EPI_DECAY) val = expf(-expf(val));
                C[(size_t)row * ldc + col] = val;
            }
        }
    }
}

__global__ void tanh_sum_kernel() {
    int i = blockIdx.x * 256 + threadIdx.x;
    if (i >= MM * 64) return;
    float s = g_wt4[i] + g_wt4[i + MM * 64] + g_wt4[i + 2 * MM * 64] + g_wt4[i + 3 * MM * 64];
    g_wt[i] = tanhf(s);
}

// ------------------------- merged weight prep -------------------------------
#define PN0 (160*HID)
#define PN1 (KD*HID)
#define PN2 (KD*HID)
#define PN3 (VD*HID)
#define PN4 (VD*HID)
#define PN5 (HID*VD)
#define PN6 (HID*160)
#define PTOT (PN0+PN1+PN2+PN3+PN4+PN5+PN6)

__global__ void prep_weights(const float* __restrict__ Wx0, const float* __restrict__ Wr,
                             const float* __restrict__ Wk, const float* __restrict__ Wv,
                             const float* __restrict__ Wg, const float* __restrict__ Wo,
                             const float* __restrict__ Wx2) {
    int i = blockIdx.x * 256 + threadIdx.x;
    if (i >= PTOT) return;
    if (i < PN0) { g_Wx0r[i] = tf32r(Wx0[i]); return; }
    i -= PN0;
    if (i < PN1) { g_Wrk[i] = tf32r(Wr[i]); return; }
    i -= PN1;
    if (i < PN2) { g_Wrk[(size_t)KD * HID + i] = tf32r(Wk[i]); return; }
    i -= PN2;
    if (i < PN3) { g_Wvg[i] = tf32r(Wv[i]); return; }
    i -= PN3;
    if (i < PN4) { g_Wvg[(size_t)VD * HID + i] = tf32r(Wg[i]); return; }
    i -= PN4;
    if (i < PN5) { g_Wor[i] = tf32r(Wo[i]); return; }
    i -= PN5;
    g_Wx2r[i] = tf32r(Wx2[i]);
}

// ------------------------- elementwise kernels ------------------------------
__global__ void lerp0_kernel(const float* __restrict__ x, const float* __restrict__ mu0) {
    size_t i = (size_t)blockIdx.x * 256 + threadIdx.x;
    if (i >= (size_t)MM * HID) return;
    int h = (int)(i & (HID - 1));
    size_t bt = i >> 10;
    int t = (int)(bt & (TT - 1));
    float xv = x[i];
    float sh = (t == 0) ? 0.f : x[i - HID];
    g_A0[i] = tf32r(xv + (sh - xv) * mu0[h]);
}

__global__ void c_kernel(const float* __restrict__ bonus) {
    int w = (blockIdx.x * blockDim.x + threadIdx.x) >> 5;
    int lane = threadIdx.x & 31;
    if (w >= MM * NH) return;
    int h = w & (NH - 1);
    size_t bt = (size_t)w >> 2;
    const float* rp = g_rk + bt * KD + h * DK;
    const float* kp = g_rk + (size_t)MM * KD + bt * KD + h * DK;
    const float* up = bonus + h * DK;
    float s = 0.f;
#pragma unroll
    for (int i = lane; i < DK; i += 32) s += rp[i] * up[i] * kp[i];
#pragma unroll
    for (int off = 16; off; off >>= 1) s += __shfl_xor_sync(0xffffffffu, s, off);
    if (lane == 0) {
        int b = (int)(bt / TT), t = (int)(bt % TT);
        g_c[(size_t)(b * NH + h) * TT + t] = s;
    }
}

// ------------------------- RWKV6 recurrent scan v3 --------------------------
// 256 blocks (16 pairs x 16 chunks of 16 v-cols); 128 threads.
// Thread map: kg = tid&7 (k-octet), col = tid>>3 -> reduction over kg is a
// 3-shfl warp-local butterfly, no barrier. cp.async quad-buffered chunks of
// 8 steps -> exactly ONE __syncthreads per 8 steps.
#define SCH 8

__global__ void __launch_bounds__(128) scan_kernel() {
    const int pair = blockIdx.x >> 4;
    const int chunk16 = blockIdx.x & 15;
    const int b = pair >> 2;
    const int h = pair & 3;
    const int col0 = chunk16 * 16;
    const int tid = threadIdx.x;
    const int kg = tid & 7;          // 0..7  (k range [16kg, 16kg+16))
    const int col = tid >> 3;        // 0..15

    __shared__ __align__(16) float sr_c[4][SCH * 128];
    __shared__ __align__(16) float se_c[4][SCH * 128];
    __shared__ __align__(16) float sk_c[4][SCH * 128];
    __shared__ __align__(16) float sv_c[4][SCH * 16];
    __shared__ __align__(16) float sc_c[4][SCH];

    float S[16];
#pragma unroll
    for (int i = 0; i < 16; i++) S[i] = 0.f;

    const float* cb = g_c + (size_t)pair * TT;
    const float* rsrc = g_rk;
    const float* ksrc = g_rk + (size_t)MM * KD;
    const size_t rkbase = (size_t)(b * TT) * KD + h * DK;
    const size_t vbase  = (size_t)(b * TT) * VD + h * DV + col0;

    auto load_chunk = [&](int c, int buf) {
        const int t0 = c * SCH;
#pragma unroll
        for (int i = 0; i < 2; i++) {
            int idx = i * 128 + tid;
            int row = idx >> 5;
            int c4  = (idx & 31) * 4;
            size_t g = rkbase + (size_t)(t0 + row) * KD + c4;
            cp16(smem_u32(&sr_c[buf][row * 128 + c4]), rsrc  + g, true);
            cp16(smem_u32(&se_c[buf][row * 128 + c4]), g_dec + g, true);
            cp16(smem_u32(&sk_c[buf][row * 128 + c4]), ksrc  + g, true);
        }
        if (tid < 32) {
            int row = tid >> 2;
            int c4 = (tid & 3) * 4;
            cp16(smem_u32(&sv_c[buf][row * 16 + c4]),
                 g_vg + vbase + (size_t)(t0 + row) * VD + c4, true);
        }
        if (tid < 2) {
            cp16(smem_u32(&sc_c[buf][tid * 4]), cb + t0 + tid * 4, true);
        }
        asm volatile("cp.async.commit_group;" ::: "memory");
    };

    const int NC = TT / SCH;
    load_chunk(0, 0);
    load_chunk(1, 1);

    for (int c = 0; c < NC; c++) {
        if (c + 2 < NC) {
            load_chunk(c + 2, (c + 2) & 3);
            asm volatile("cp.async.wait_group 2;" ::: "memory");
        } else if (c + 1 < NC) {
            asm volatile("cp.async.wait_group 1;" ::: "memory");
        } else {
            asm volatile("cp.async.wait_group 0;" ::: "memory");
        }
        __syncthreads();   // the ONLY barrier per 8 steps

        const int p = c & 3;
#pragma unroll
        for (int tt = 0; tt < SCH; tt++) {
            const float vj = sv_c[p][tt * 16 + col];
            const int kb = tt * 128 + kg * 16;
            float op0 = 0.f, op1 = 0.f, op2 = 0.f, op3 = 0.f;
            {
                float4 r4 = *(const float4*)&sr_c[p][kb + 0];
                float4 e4 = *(const float4*)&se_c[p][kb + 0];
                float4 k4 = *(const float4*)&sk_c[p][kb + 0];
                op0 = fmaf(r4.x, S[0], op0); S[0] = fmaf(e4.x, S[0], k4.x * vj);
                op0 = fmaf(r4.y, S[1], op0); S[1] = fmaf(e4.y, S[1], k4.y * vj);
                op0 = fmaf(r4.z, S[2], op0); S[2] = fmaf(e4.z, S[2], k4.z * vj);
                op0 = fmaf(r4.w, S[3], op0); S[3] = fmaf(e4.w, S[3], k4.w * vj);
            }
            {
                float4 r4 = *(const float4*)&sr_c[p][kb + 4];
                float4 e4 = *(const float4*)&se_c[p][kb + 4];
                float4 k4 = *(const float4*)&sk_c[p][kb + 4];
                op1 = fmaf(r4.x, S[4], op1); S[4] = fmaf(e4.x, S[4], k4.x * vj);
                op1 = fmaf(r4.y, S[5], op1); S[5] = fmaf(e4.y, S[5], k4.y * vj);
                op1 = fmaf(r4.z, S[6], op1); S[6] = fmaf(e4.z, S[6], k4.z * vj);
                op1 = fmaf(r4.w, S[7], op1); S[7] = fmaf(e4.w, S[7], k4.w * vj);
            }
            {
                float4 r4 = *(const float4*)&sr_c[p][kb + 8];
                float4 e4 = *(const float4*)&se_c[p][kb + 8];
                float4 k4 = *(const float4*)&sk_c[p][kb + 8];
                op2 = fmaf(r4.x, S[8], op2); S[8] = fmaf(e4.x, S[8], k4.x * vj);
                op2 = fmaf(r4.y, S[9], op2); S[9] = fmaf(e4.y, S[9], k4.y * vj);
                op2 = fmaf(r4.z, S[10], op2); S[10] = fmaf(e4.z, S[10], k4.z * vj);
                op2 = fmaf(r4.w, S[11], op2); S[11] = fmaf(e4.w, S[11], k4.w * vj);
            }
            {
                float4 r4 = *(const float4*)&sr_c[p][kb + 12];
                float4 e4 = *(const float4*)&se_c[p][kb + 12];
                float4 k4 = *(const float4*)&sk_c[p][kb + 12];
                op3 = fmaf(r4.x, S[12], op3); S[12] = fmaf(e4.x, S[12], k4.x * vj);
                op3 = fmaf(r4.y, S[13], op3); S[13] = fmaf(e4.y, S[13], k4.y * vj);
                op3 = fmaf(r4.z, S[14], op3); S[14] = fmaf(e4.z, S[14], k4.z * vj);
                op3 = fmaf(r4.w, S[15], op3); S[15] = fmaf(e4.w, S[15], k4.w * vj);
            }
            float op = (op0 + op1) + (op2 + op3);
            op += __shfl_xor_sync(0xffffffffu, op, 1);
            op += __shfl_xor_sync(0xffffffffu, op, 2);
            op += __shfl_xor_sync(0xffffffffu, op, 4);
            if (kg == 0) {
                float o = op + sv_c[p][tt * 16 + col] * sc_c[p][tt];
                g_o[vbase + (size_t)(c * SCH + tt) * VD + col] = o;
            }
        }
    }
}

// ------------------------- GroupNorm + swish gate ---------------------------
__global__ void gn_gate_kernel(const float* __restrict__ gnw, const float* __restrict__ gnb) {
    size_t bt = (size_t)(blockIdx.x >> 2);
    int h = blockIdx.x & 3;
    int j = threadIdx.x;
    size_t idx = bt * VD + h * DV + j;
    float val = g_o[idx];

    __shared__ float ssum[8], ssq[8];
    float s = val, q = val * val;
#pragma unroll
    for (int off = 16; off; off >>= 1) {
        s += __shfl_xor_sync(0xffffffffu, s, off);
        q += __shfl_xor_sync(0xffffffffu, q, off);
    }
    int wid = threadIdx.x >> 5, lane = threadIdx.x & 31;
    if (lane == 0) { ssum[wid] = s; ssq[wid] = q; }
    __syncthreads();
    if (threadIdx.x == 0) {
        float ts = 0.f, tq = 0.f;
#pragma unroll
        for (int i = 0; i < 8; i++) { ts += ssum[i]; tq += ssq[i]; }
        ssum[0] = ts; ssq[0] = tq;
    }
    __syncthreads();
    float mean = ssum[0] * (1.f / DV);
    float var = ssq[0] * (1.f / DV) - mean * mean;
    float ny = (val - mean) * rsqrtf(var + 1e-5f) * gnw[h * DV + j] + gnb[h * DV + j];
    float gv = g_vg[(size_t)MM * VD + idx];
    float sig = 1.f / (1.f + expf(-gv));
    g_gate[idx] = tf32r(ny * gv * sig);
}

// ------------------------- launch ------------------------------------------
extern "C" void kernel_launch(void* const* d_in, const int* in_sizes, int n_in,
                              void* d_out, int out_size) {
    const float* x      = (const float*)d_in[0];
    const float* mu0    = (const float*)d_in[1];
    const float* W_x0   = (const float*)d_in[2];
    const float* W_x2   = (const float*)d_in[3];
    const float* x_bias = (const float*)d_in[4];
    const float* W_r    = (const float*)d_in[5];
    const float* W_w1   = (const float*)d_in[6];
    const float* W_w2   = (const float*)d_in[7];
    const float* b_w2   = (const float*)d_in[8];
    const float* W_k    = (const float*)d_in[9];
    const float* W_v    = (const float*)d_in[10];
    const float* W_g    = (const float*)d_in[11];
    const float* bonus  = (const float*)d_in[12];
    const float* gnw    = (const float*)d_in[13];
    const float* gnb    = (const float*)d_in[14];
    const float* W_o    = (const float*)d_in[15];
    float* out = (float*)d_out;

    float *pA0, *pxp, *pA5, *prk, *pdec, *pwt4, *pwt, *pvg, *pgate;
    float *pWx0r, *pWrk, *pWvg, *pWor, *pWx2r;
    cudaGetSymbolAddress((void**)&pA0, g_A0);
    cudaGetSymbolAddress((void**)&pxp, g_xp);
    cudaGetSymbolAddress((void**)&pA5, g_A5);
    cudaGetSymbolAddress((void**)&prk, g_rk);
    cudaGetSymbolAddress((void**)&pdec, g_dec);
    cudaGetSymbolAddress((void**)&pwt4, g_wt4);
    cudaGetSymbolAddress((void**)&pwt, g_wt);
    cudaGetSymbolAddress((void**)&pvg, g_vg);
    cudaGetSymbolAddress((void**)&pgate, g_gate);
    cudaGetSymbolAddress((void**)&pWx0r, g_Wx0r);
    cudaGetSymbolAddress((void**)&pWrk, g_Wrk);
    cudaGetSymbolAddress((void**)&pWvg, g_Wvg);
    cudaGetSymbolAddress((void**)&pWor, g_Wor);
    cudaGetSymbolAddress((void**)&pWx2r, g_Wx2r);

    const size_t ASTRIDE = (size_t)MM * HID;
    float* pAr = pA5 + 0 * ASTRIDE;
    float* pAw = pA5 + 1 * ASTRIDE;
    float* pAv = pA5 + 3 * ASTRIDE;

    const int SMEMSZ = 4 * SMBUF * (int)sizeof(float);  // 73728
    cudaFuncSetAttribute(gemm_mma<EPI_NONE>, cudaFuncAttributeMaxDynamicSharedMemorySize, SMEMSZ);
    cudaFuncSetAttribute(gemm_mma<EPI_TANH>, cudaFuncAttributeMaxDynamicSharedMemorySize, SMEMSZ);
    cudaFuncSetAttribute(gemm_mma<EPI_LERP>, cudaFuncAttributeMaxDynamicSharedMemorySize, SMEMSZ);

    const int EW_BLOCKS = (MM * HID + 255) / 256;

    // 1) merged weight prep
    prep_weights<<<(PTOT + 255) / 256, 256>>>(W_x0, W_r, W_k, W_v, W_g, W_o, W_x2);

    // 2) lerp0
    lerp0_kernel<<<EW_BLOCKS, 256>>>(x, mu0);

    // 3) xp = tanh(A0 @ W_x0^T)  [8192 x 160 x 1024]
    gemm_mma<EPI_TANH><<<dim3(2, 64), 256, SMEMSZ>>>(pA0, pWx0r, nullptr, pxp,
                                                     160, 1024, 1024, 1024, 160,
                                                     0, 0, 0, 0, nullptr);

    // 4) fused mus+lerp [8192 x 1024 x 32] x5 over z
    gemm_mma<EPI_LERP><<<dim3(8, 64, 5), 256, SMEMSZ>>>(pxp, pWx2r, x_bias, pA5,
                                                        1024, 32, 160, 160, 1024,
                                                        32, 32, 1024, ASTRIDE, x);

    // 5) merged r+k projections (z=2)
    gemm_mma<EPI_NONE><<<dim3(4, 64, 2), 256, SMEMSZ>>>(pAr, pWrk, nullptr, prk,
                                                        KD, 1024, 1024, 1024, KD,
                                                        2 * ASTRIDE, (size_t)KD * HID, 0, (size_t)MM * KD, nullptr);
    // 6) merged v+g projections (z=2)
    gemm_mma<EPI_NONE><<<dim3(8, 64, 2), 256, SMEMSZ>>>(pAv, pWvg, nullptr, pvg,
                                                        VD, 1024, 1024, 1024, VD,
                                                        ASTRIDE, (size_t)VD * HID, 0, (size_t)MM * VD, nullptr);

    // 7-9) w path (fp32): split-K w1 -> sum+tanh -> w2 decay
    sgemm_nt<EPI_NONE><<<dim3(1, 64, 4), 256>>>(pAw, W_w1, nullptr, pwt4,
                                                MM, 64, 256, 1024, 1024, 64,
                                                256, 256, MM * 64);
    tanh_sum_kernel<<<(MM * 64 + 255) / 256, 256>>>();
    sgemm_nt<EPI_DECAY><<<dim3(4, 64), 256>>>(pwt, W_w2, b_w2, pdec,
                                              MM, KD, 64, 64, 64, KD, 0, 0, 0);

    // 10-12) bonus scalar, recurrent scan v3, groupnorm+gate
    c_kernel<<<(MM * NH * 32 + 255) / 256, 256>>>(bonus);
    scan_kernel<<<256, 128>>>();
    gn_gate_kernel<<<MM * NH, 256>>>(gnw, gnb);

    // 13) output projection [8192 x 1024 x 1024]
    gemm_mma<EPI_NONE><<<dim3(8, 64), 256, SMEMSZ>>>(pgate, pWor, nullptr, out,
                                                     HID, 1024, 1024, 1024, HID,
                                                     0, 0, 0, 0, nullptr);
}

// round 14
// speedup vs baseline: 2.2055x; 2.2055x over previous
#include <cuda_runtime.h>
#include <cuda_bf16.h>
#include <cstdint>
#include <math.h>

// ---------------------------------------------------------------------------
// RWKV6Attention: B=4, T=2048, HID=1024, NH=4, KD=512, VD=1024, DK=128, DV=256
// Round 14: Round-12 base (best: 1099us) + scan-only tweaks:
//   (a) 4-way op accumulators (shorten per-step dependency chain),
//   (b) single reduction barrier per 8 steps (pbuf[8][8][16]).
// Thread map and cp.async staging identical to Round 12.
// ---------------------------------------------------------------------------

#define BB 4
#define TT 2048
#define HID 1024
#define NH 4
#define KD 512
#define VD 1024
#define DK 128
#define DV 256
#define MM (BB*TT)   // 8192

// ------------------------- scratch (device globals) ------------------------
__device__ float g_A0  [(size_t)MM*HID];
__device__ float g_xp  [(size_t)MM*160];
__device__ float g_A5  [(size_t)5*MM*HID];   // slot-major: r,w,k,v,g
__device__ float g_rk  [(size_t)2*MM*KD];    // slot 0: r, slot 1: k
__device__ float g_dec [(size_t)MM*KD];
__device__ float g_wt4 [(size_t)4*MM*64];
__device__ float g_wt  [(size_t)MM*64];
__device__ float g_vg  [(size_t)2*MM*VD];    // slot 0: v, slot 1: g
__device__ float g_c   [(size_t)BB*NH*TT];
__device__ float g_o   [(size_t)MM*VD];
__device__ float g_gate[(size_t)MM*VD];

// tf32-rounded weights
__device__ float g_Wx0r[160*HID];
__device__ float g_Wrk [(size_t)2*KD*HID];
__device__ float g_Wvg [(size_t)2*VD*HID];
__device__ float g_Wor [HID*VD];
__device__ float g_Wx2r[HID*160];

// ------------------------- helpers -----------------------------------------
__device__ __forceinline__ uint32_t smem_u32(const void* p) {
    uint32_t a;
    asm("{ .reg .u64 t; cvta.to.shared.u64 t, %1; cvt.u32.u64 %0, t; }" : "=r"(a) : "l"(p));
    return a;
}
__device__ __forceinline__ float tf32r(float x) {
    uint32_t u;
    asm("cvt.rna.tf32.f32 %0, %1;" : "=r"(u) : "f"(x));
    return __uint_as_float(u);
}
__device__ __forceinline__ void cp16(uint32_t dst, const void* src, bool pred) {
    asm volatile("cp.async.ca.shared.global [%0], [%1], 16, %2;"
                 :: "r"(dst), "l"(src), "r"(pred ? 16u : 0u));
}
__device__ __forceinline__ void mma1688(float* c, const uint32_t* a, const uint32_t* b) {
    asm volatile(
        "mma.sync.aligned.m16n8k8.row.col.f32.tf32.tf32.f32 "
        "{%0,%1,%2,%3}, {%4,%5,%6,%7}, {%8,%9}, {%0,%1,%2,%3};"
        : "+f"(c[0]), "+f"(c[1]), "+f"(c[2]), "+f"(c[3])
        : "r"(a[0]), "r"(a[1]), "r"(a[2]), "r"(a[3]), "r"(b[0]), "r"(b[1]));
}

// ------------------------- tf32 mma.sync GEMM -------------------------------
enum { EPI_NONE = 0, EPI_TANH = 1, EPI_DECAY = 2, EPI_LERP = 3 };

#define SMPAD 36
#define SMBUF (128*SMPAD)

template <int EPI>
__global__ void __launch_bounds__(256) gemm_mma(
    const float* __restrict__ A, const float* __restrict__ W,
    const float* __restrict__ bias, float* __restrict__ C,
    int N, int K, int lda, int ldw, int ldc,
    size_t zsA, size_t zsW, size_t zsB, size_t zsC,
    const float* __restrict__ X)
{
    extern __shared__ float sm[];
    float* sA = sm;                    // [2][SMBUF]
    float* sB = sm + 2 * SMBUF;        // [2][SMBUF]

    const int z = blockIdx.z;
    A += (size_t)z * zsA;
    W += (size_t)z * zsW;
    if (bias) bias += (size_t)z * zsB;
    C += (size_t)z * zsC;

    const int tid = threadIdx.x;
    const int lane = tid & 31;
    const int wid = tid >> 5;
    const int bm = blockIdx.y * 128;
    const int bn = blockIdx.x * 128;
    const int wm = (wid >> 2) * 64;
    const int wn = (wid & 3) * 32;
    const int grp = lane >> 2;
    const int tg = lane & 3;

    float acc[4][4][4];
#pragma unroll
    for (int i = 0; i < 4; i++)
#pragma unroll
        for (int j = 0; j < 4; j++)
#pragma unroll
            for (int q = 0; q < 4; q++) acc[i][j][q] = 0.f;

    auto load_tiles = [&](int ks, int buf) {
#pragma unroll
        for (int i = 0; i < 4; i++) {
            int idx = i * 256 + tid;
            int row = idx >> 3, c4 = idx & 7;
            const float* srcA = A + (size_t)(bm + row) * lda + ks * 32 + c4 * 4;
            cp16(smem_u32(sA + buf * SMBUF + row * SMPAD + c4 * 4), srcA, true);
            int gn = bn + row;
            bool ok = gn < N;
            const float* srcB = W + (size_t)(ok ? gn : 0) * ldw + ks * 32 + c4 * 4;
            cp16(smem_u32(sB + buf * SMBUF + row * SMPAD + c4 * 4), srcB, ok);
        }
        asm volatile("cp.async.commit_group;" ::: "memory");
    };

    const int S = K >> 5;
    load_tiles(0, 0);

    for (int s = 0; s < S; s++) {
        const int buf = s & 1;
        if (s + 1 < S) {
            load_tiles(s + 1, buf ^ 1);
            asm volatile("cp.async.wait_group 1;" ::: "memory");
        } else {
            asm volatile("cp.async.wait_group 0;" ::: "memory");
        }
        __syncthreads();

        const float* pA = sA + buf * SMBUF + wm * SMPAD;
        const float* pB = sB + buf * SMBUF + wn * SMPAD;
#pragma unroll
        for (int kk = 0; kk < 4; kk++) {
            const int kb = kk * 8;
            uint32_t a[4][4], b[4][2];
#pragma unroll
            for (int mt = 0; mt < 4; mt++) {
                int r0 = mt * 16 + grp;
                a[mt][0] = __float_as_uint(pA[r0 * SMPAD + kb + tg]);
                a[mt][1] = __float_as_uint(pA[(r0 + 8) * SMPAD + kb + tg]);
                a[mt][2] = __float_as_uint(pA[r0 * SMPAD + kb + tg + 4]);
                a[mt][3] = __float_as_uint(pA[(r0 + 8) * SMPAD + kb + tg + 4]);
            }
#pragma unroll
            for (int nt = 0; nt < 4; nt++) {
                int c0 = nt * 8 + grp;
                b[nt][0] = __float_as_uint(pB[c0 * SMPAD + kb + tg]);
                b[nt][1] = __float_as_uint(pB[c0 * SMPAD + kb + tg + 4]);
            }
#pragma unroll
            for (int mt = 0; mt < 4; mt++)
#pragma unroll
                for (int nt = 0; nt < 4; nt++)
                    mma1688(acc[mt][nt], a[mt], b[nt]);
        }
        __syncthreads();
    }

    // epilogue
#pragma unroll
    for (int mt = 0; mt < 4; mt++) {
#pragma unroll
        for (int nt = 0; nt < 4; nt++) {
            int col = bn + wn + nt * 8 + tg * 2;
            if (col >= N) continue;
            float bv0 = bias ? bias[col] : 0.f;
            float bv1 = bias ? bias[col + 1] : 0.f;
#pragma unroll
            for (int half = 0; half < 2; half++) {
                int row = bm + wm + mt * 16 + grp + half * 8;
                float v0 = acc[mt][nt][half * 2 + 0] + bv0;
                float v1 = acc[mt][nt][half * 2 + 1] + bv1;
                if (EPI == EPI_TANH)  { v0 = tf32r(tanhf(v0)); v1 = tf32r(tanhf(v1)); }
                if (EPI == EPI_DECAY) { v0 = expf(-expf(v0)); v1 = expf(-expf(v1)); }
                if (EPI == EPI_LERP) {
                    size_t xi = (size_t)row * HID + col;
                    float2 xv = *(const float2*)&X[xi];
                    int t = row & (TT - 1);
                    float2 sh = (t == 0) ? make_float2(0.f, 0.f)
                                         : *(const float2*)&X[xi - HID];
                    v0 = xv.x + (sh.x - xv.x) * v0;
                    v1 = xv.y + (sh.y - xv.y) * v1;
                    if (z != 1) { v0 = tf32r(v0); v1 = tf32r(v1); }  // w slot stays fp32
                }
                *(float2*)&C[(size_t)row * ldc + col] = make_float2(v0, v1);
            }
        }
    }
}

// ------------------------- fp32 SGEMM (w path) ------------------------------
template <int EPI>
__global__ void sgemm_nt(const float* __restrict__ A, const float* __restrict__ W,
                         const float* __restrict__ bias, float* __restrict__ C,
                         int M, int N, int K, int lda, int ldw, int ldc,
                         int zsA, int zsW, int zsC) {
    __shared__ float As[8][128];
    __shared__ float Ws[8][128];
    const int z = blockIdx.z;
    A += (size_t)z * zsA;
    W += (size_t)z * zsW;
    C += (size_t)z * zsC;

    const int tid = threadIdx.x;
    const int bm = blockIdx.y * 128;
    const int bn = blockIdx.x * 128;
    const int lr = tid >> 1;
    const int lc = (tid & 1) << 2;
    const int tx = tid & 15;
    const int ty = tid >> 4;

    float acc[8][8];
#pragma unroll
    for (int i = 0; i < 8; i++)
#pragma unroll
        for (int j = 0; j < 8; j++) acc[i][j] = 0.f;

    const bool wok = (bn + lr) < N;
    const float* Aptr = A + (size_t)(bm + lr) * lda + lc;
    const float* Wptr = W + (size_t)(wok ? (bn + lr) : 0) * ldw + lc;

    for (int k0 = 0; k0 < K; k0 += 8) {
        float4 av = *(const float4*)(Aptr + k0);
        float4 wv = wok ? *(const float4*)(Wptr + k0) : make_float4(0.f, 0.f, 0.f, 0.f);
        As[lc + 0][lr] = av.x; As[lc + 1][lr] = av.y; As[lc + 2][lr] = av.z; As[lc + 3][lr] = av.w;
        Ws[lc + 0][lr] = wv.x; Ws[lc + 1][lr] = wv.y; Ws[lc + 2][lr] = wv.z; Ws[lc + 3][lr] = wv.w;
        __syncthreads();
#pragma unroll
        for (int kk = 0; kk < 8; kk++) {
            float a[8], b[8];
            *(float4*)&a[0] = *(const float4*)&As[kk][ty * 8];
            *(float4*)&a[4] = *(const float4*)&As[kk][ty * 8 + 4];
            *(float4*)&b[0] = *(const float4*)&Ws[kk][tx * 8];
            *(float4*)&b[4] = *(const float4*)&Ws[kk][tx * 8 + 4];
#pragma unroll
            for (int i = 0; i < 8; i++)
#pragma unroll
                for (int j = 0; j < 8; j++) acc[i][j] = fmaf(a[i], b[j], acc[i][j]);
        }
        __syncthreads();
    }

#pragma unroll
    for (int i = 0; i < 8; i++) {
        int row = bm + ty * 8 + i;
#pragma unroll
        for (int j = 0; j < 8; j++) {
            int col = bn + tx * 8 + j;
            if (col < N) {
                float val = acc[i][j];
                if (bias) val += bias[col];
                if (EPI == EPI_TANH)  val = tanhf(val);
                if (EPI == EPI_DECAY) val = expf(-expf(val));
                C[(size_t)row * ldc + col] = val;
            }
        }
    }
}

__global__ void tanh_sum_kernel() {
    int i = blockIdx.x * 256 + threadIdx.x;
    if (i >= MM * 64) return;
    float s = g_wt4[i] + g_wt4[i + MM * 64] + g_wt4[i + 2 * MM * 64] + g_wt4[i + 3 * MM * 64];
    g_wt[i] = tanhf(s);
}

// ------------------------- merged weight prep -------------------------------
#define PN0 (160*HID)
#define PN1 (KD*HID)
#define PN2 (KD*HID)
#define PN3 (VD*HID)
#define PN4 (VD*HID)
#define PN5 (HID*VD)
#define PN6 (HID*160)
#define PTOT (PN0+PN1+PN2+PN3+PN4+PN5+PN6)

__global__ void prep_weights(const float* __restrict__ Wx0, const float* __restrict__ Wr,
                             const float* __restrict__ Wk, const float* __restrict__ Wv,
                             const float* __restrict__ Wg, const float* __restrict__ Wo,
                             const float* __restrict__ Wx2) {
    int i = blockIdx.x * 256 + threadIdx.x;
    if (i >= PTOT) return;
    if (i < PN0) { g_Wx0r[i] = tf32r(Wx0[i]); return; }
    i -= PN0;
    if (i < PN1) { g_Wrk[i] = tf32r(Wr[i]); return; }
    i -= PN1;
    if (i < PN2) { g_Wrk[(size_t)KD * HID + i] = tf32r(Wk[i]); return; }
    i -= PN2;
    if (i < PN3) { g_Wvg[i] = tf32r(Wv[i]); return; }
    i -= PN3;
    if (i < PN4) { g_Wvg[(size_t)VD * HID + i] = tf32r(Wg[i]); return; }
    i -= PN4;
    if (i < PN5) { g_Wor[i] = tf32r(Wo[i]); return; }
    i -= PN5;
    g_Wx2r[i] = tf32r(Wx2[i]);
}

// ------------------------- elementwise kernels ------------------------------
__global__ void lerp0_kernel(const float* __restrict__ x, const float* __restrict__ mu0) {
    size_t i = (size_t)blockIdx.x * 256 + threadIdx.x;
    if (i >= (size_t)MM * HID) return;
    int h = (int)(i & (HID - 1));
    size_t bt = i >> 10;
    int t = (int)(bt & (TT - 1));
    float xv = x[i];
    float sh = (t == 0) ? 0.f : x[i - HID];
    g_A0[i] = tf32r(xv + (sh - xv) * mu0[h]);
}

__global__ void c_kernel(const float* __restrict__ bonus) {
    int w = (blockIdx.x * blockDim.x + threadIdx.x) >> 5;
    int lane = threadIdx.x & 31;
    if (w >= MM * NH) return;
    int h = w & (NH - 1);
    size_t bt = (size_t)w >> 2;
    const float* rp = g_rk + bt * KD + h * DK;
    const float* kp = g_rk + (size_t)MM * KD + bt * KD + h * DK;
    const float* up = bonus + h * DK;
    float s = 0.f;
#pragma unroll
    for (int i = lane; i < DK; i += 32) s += rp[i] * up[i] * kp[i];
#pragma unroll
    for (int off = 16; off; off >>= 1) s += __shfl_xor_sync(0xffffffffu, s, off);
    if (lane == 0) {
        int b = (int)(bt / TT), t = (int)(bt % TT);
        g_c[(size_t)(b * NH + h) * TT + t] = s;
    }
}

// ------------------------- RWKV6 recurrent scan (R12 map + short chains) ----
// 256 blocks (16 pairs x 16 chunks of 16 v-cols); 128 threads = 8 kg x 16 col
// (kg = tid>>4: broadcast-friendly smem reads, as in Round 12).
// cp.async double-buffered 8-step chunks; pbuf[8][8][16] lets ALL outputs of a
// chunk be reduced after ONE barrier (tt = tid>>4, col = tid&15).
#define SCH 8

__global__ void __launch_bounds__(128) scan_kernel() {
    const int pair = blockIdx.x >> 4;
    const int chunk16 = blockIdx.x & 15;
    const int b = pair >> 2;
    const int h = pair & 3;
    const int col0 = chunk16 * 16;
    const int tid = threadIdx.x;
    const int kg = tid >> 4;         // 0..7
    const int col = tid & 15;        // 0..15

    __shared__ __align__(16) float sr_c[2][SCH * 128];
    __shared__ __align__(16) float se_c[2][SCH * 128];
    __shared__ __align__(16) float sk_c[2][SCH * 128];
    __shared__ __align__(16) float sv_c[2][SCH * 16];
    __shared__ __align__(16) float sc_c[2][SCH];
    __shared__ float pbuf[SCH][8][16];

    float S[16];
#pragma unroll
    for (int i = 0; i < 16; i++) S[i] = 0.f;

    const float* cb = g_c + (size_t)pair * TT;
    const float* rsrc = g_rk;
    const float* ksrc = g_rk + (size_t)MM * KD;
    const size_t rkbase = (size_t)(b * TT) * KD + h * DK;
    const size_t vbase  = (size_t)(b * TT) * VD + h * DV + col0;

    auto load_chunk = [&](int c, int buf) {
        const int t0 = c * SCH;
#pragma unroll
        for (int i = 0; i < 2; i++) {
            int idx = i * 128 + tid;
            int row = idx >> 5;
            int c4  = (idx & 31) * 4;
            size_t g = rkbase + (size_t)(t0 + row) * KD + c4;
            cp16(smem_u32(&sr_c[buf][row * 128 + c4]), rsrc  + g, true);
            cp16(smem_u32(&se_c[buf][row * 128 + c4]), g_dec + g, true);
            cp16(smem_u32(&sk_c[buf][row * 128 + c4]), ksrc  + g, true);
        }
        if (tid < 32) {
            int row = tid >> 2;
            int c4 = (tid & 3) * 4;
            cp16(smem_u32(&sv_c[buf][row * 16 + c4]),
                 g_vg + vbase + (size_t)(t0 + row) * VD + c4, true);
        }
        if (tid < 2) {
            cp16(smem_u32(&sc_c[buf][tid * 4]), cb + t0 + tid * 4, true);
        }
        asm volatile("cp.async.commit_group;" ::: "memory");
    };

    load_chunk(0, 0);
    const int NC = TT / SCH;

    for (int c = 0; c < NC; c++) {
        const int p = c & 1;
        if (c + 1 < NC) {
            load_chunk(c + 1, p ^ 1);
            asm volatile("cp.async.wait_group 1;" ::: "memory");
        } else {
            asm volatile("cp.async.wait_group 0;" ::: "memory");
        }
        __syncthreads();   // buffer p ready; protects buffer p^1 reuse

#pragma unroll
        for (int tt = 0; tt < SCH; tt++) {
            const float vj = sv_c[p][tt * 16 + col];
            const int kb = tt * 128 + kg * 16;
            float op0 = 0.f, op1 = 0.f, op2 = 0.f, op3 = 0.f;
            {
                float4 r4 = *(const float4*)&sr_c[p][kb + 0];
                float4 e4 = *(const float4*)&se_c[p][kb + 0];
                float4 k4 = *(const float4*)&sk_c[p][kb + 0];
                op0 = fmaf(r4.x, S[0], op0); S[0] = fmaf(e4.x, S[0], k4.x * vj);
                op0 = fmaf(r4.y, S[1], op0); S[1] = fmaf(e4.y, S[1], k4.y * vj);
                op0 = fmaf(r4.z, S[2], op0); S[2] = fmaf(e4.z, S[2], k4.z * vj);
                op0 = fmaf(r4.w, S[3], op0); S[3] = fmaf(e4.w, S[3], k4.w * vj);
            }
            {
                float4 r4 = *(const float4*)&sr_c[p][kb + 4];
                float4 e4 = *(const float4*)&se_c[p][kb + 4];
                float4 k4 = *(const float4*)&sk_c[p][kb + 4];
                op1 = fmaf(r4.x, S[4], op1); S[4] = fmaf(e4.x, S[4], k4.x * vj);
                op1 = fmaf(r4.y, S[5], op1); S[5] = fmaf(e4.y, S[5], k4.y * vj);
                op1 = fmaf(r4.z, S[6], op1); S[6] = fmaf(e4.z, S[6], k4.z * vj);
                op1 = fmaf(r4.w, S[7], op1); S[7] = fmaf(e4.w, S[7], k4.w * vj);
            }
            {
                float4 r4 = *(const float4*)&sr_c[p][kb + 8];
                float4 e4 = *(const float4*)&se_c[p][kb + 8];
                float4 k4 = *(const float4*)&sk_c[p][kb + 8];
                op2 = fmaf(r4.x, S[8], op2);  S[8]  = fmaf(e4.x, S[8],  k4.x * vj);
                op2 = fmaf(r4.y, S[9], op2);  S[9]  = fmaf(e4.y, S[9],  k4.y * vj);
                op2 = fmaf(r4.z, S[10], op2); S[10] = fmaf(e4.z, S[10], k4.z * vj);
                op2 = fmaf(r4.w, S[11], op2); S[11] = fmaf(e4.w, S[11], k4.w * vj);
            }
            {
                float4 r4 = *(const float4*)&sr_c[p][kb + 12];
                float4 e4 = *(const float4*)&se_c[p][kb + 12];
                float4 k4 = *(const float4*)&sk_c[p][kb + 12];
                op3 = fmaf(r4.x, S[12], op3); S[12] = fmaf(e4.x, S[12], k4.x * vj);
                op3 = fmaf(r4.y, S[13], op3); S[13] = fmaf(e4.y, S[13], k4.y * vj);
                op3 = fmaf(r4.z, S[14], op3); S[14] = fmaf(e4.z, S[14], k4.z * vj);
                op3 = fmaf(r4.w, S[15], op3); S[15] = fmaf(e4.w, S[15], k4.w * vj);
            }
            pbuf[tt][kg][col] = (op0 + op1) + (op2 + op3);
        }
        __syncthreads();   // ONE reduction barrier per 8 steps

        {   // 128 threads cover all (tt, col) outputs of this chunk
            const int tt = tid >> 4;
            const int jc = tid & 15;
            float o = pbuf[tt][0][jc] + pbuf[tt][1][jc] + pbuf[tt][2][jc] + pbuf[tt][3][jc]
                    + pbuf[tt][4][jc] + pbuf[tt][5][jc] + pbuf[tt][6][jc] + pbuf[tt][7][jc]
                    + sv_c[p][tt * 16 + jc] * sc_c[p][tt];
            g_o[vbase + (size_t)(c * SCH + tt) * VD + jc] = o;
        }
        __syncthreads();   // pbuf/staging safe before next chunk
    }
}

// ------------------------- GroupNorm + swish gate ---------------------------
__global__ void gn_gate_kernel(const float* __restrict__ gnw, const float* __restrict__ gnb) {
    size_t bt = (size_t)(blockIdx.x >> 2);
    int h = blockIdx.x & 3;
    int j = threadIdx.x;
    size_t idx = bt * VD + h * DV + j;
    float val = g_o[idx];

    __shared__ float ssum[8], ssq[8];
    float s = val, q = val * val;
#pragma unroll
    for (int off = 16; off; off >>= 1) {
        s += __shfl_xor_sync(0xffffffffu, s, off);
        q += __shfl_xor_sync(0xffffffffu, q, off);
    }
    int wid = threadIdx.x >> 5, lane = threadIdx.x & 31;
    if (lane == 0) { ssum[wid] = s; ssq[wid] = q; }
    __syncthreads();
    if (threadIdx.x == 0) {
        float ts = 0.f, tq = 0.f;
#pragma unroll
        for (int i = 0; i < 8; i++) { ts += ssum[i]; tq += ssq[i]; }
        ssum[0] = ts; ssq[0] = tq;
    }
    __syncthreads();
    float mean = ssum[0] * (1.f / DV);
    float var = ssq[0] * (1.f / DV) - mean * mean;
    float ny = (val - mean) * rsqrtf(var + 1e-5f) * gnw[h * DV + j] + gnb[h * DV + j];
    float gv = g_vg[(size_t)MM * VD + idx];
    float sig = 1.f / (1.f + expf(-gv));
    g_gate[idx] = tf32r(ny * gv * sig);
}

// ------------------------- launch ------------------------------------------
extern "C" void kernel_launch(void* const* d_in, const int* in_sizes, int n_in,
                              void* d_out, int out_size) {
    const float* x      = (const float*)d_in[0];
    const float* mu0    = (const float*)d_in[1];
    const float* W_x0   = (const float*)d_in[2];
    const float* W_x2   = (const float*)d_in[3];
    const float* x_bias = (const float*)d_in[4];
    const float* W_r    = (const float*)d_in[5];
    const float* W_w1   = (const float*)d_in[6];
    const float* W_w2   = (const float*)d_in[7];
    const float* b_w2   = (const float*)d_in[8];
    const float* W_k    = (const float*)d_in[9];
    const float* W_v    = (const float*)d_in[10];
    const float* W_g    = (const float*)d_in[11];
    const float* bonus  = (const float*)d_in[12];
    const float* gnw    = (const float*)d_in[13];
    const float* gnb    = (const float*)d_in[14];
    const float* W_o    = (const float*)d_in[15];
    float* out = (float*)d_out;

    float *pA0, *pxp, *pA5, *prk, *pdec, *pwt4, *pwt, *pvg, *pgate;
    float *pWx0r, *pWrk, *pWvg, *pWor, *pWx2r;
    cudaGetSymbolAddress((void**)&pA0, g_A0);
    cudaGetSymbolAddress((void**)&pxp, g_xp);
    cudaGetSymbolAddress((void**)&pA5, g_A5);
    cudaGetSymbolAddress((void**)&prk, g_rk);
    cudaGetSymbolAddress((void**)&pdec, g_dec);
    cudaGetSymbolAddress((void**)&pwt4, g_wt4);
    cudaGetSymbolAddress((void**)&pwt, g_wt);
    cudaGetSymbolAddress((void**)&pvg, g_vg);
    cudaGetSymbolAddress((void**)&pgate, g_gate);
    cudaGetSymbolAddress((void**)&pWx0r, g_Wx0r);
    cudaGetSymbolAddress((void**)&pWrk, g_Wrk);
    cudaGetSymbolAddress((void**)&pWvg, g_Wvg);
    cudaGetSymbolAddress((void**)&pWor, g_Wor);
    cudaGetSymbolAddress((void**)&pWx2r, g_Wx2r);

    const size_t ASTRIDE = (size_t)MM * HID;
    float* pAr = pA5 + 0 * ASTRIDE;
    float* pAw = pA5 + 1 * ASTRIDE;
    float* pAv = pA5 + 3 * ASTRIDE;

    const int SMEMSZ = 4 * SMBUF * (int)sizeof(float);  // 73728
    cudaFuncSetAttribute(gemm_mma<EPI_NONE>, cudaFuncAttributeMaxDynamicSharedMemorySize, SMEMSZ);
    cudaFuncSetAttribute(gemm_mma<EPI_TANH>, cudaFuncAttributeMaxDynamicSharedMemorySize, SMEMSZ);
    cudaFuncSetAttribute(gemm_mma<EPI_LERP>, cudaFuncAttributeMaxDynamicSharedMemorySize, SMEMSZ);

    const int EW_BLOCKS = (MM * HID + 255) / 256;

    // 1) merged weight prep
    prep_weights<<<(PTOT + 255) / 256, 256>>>(W_x0, W_r, W_k, W_v, W_g, W_o, W_x2);

    // 2) lerp0
    lerp0_kernel<<<EW_BLOCKS, 256>>>(x, mu0);

    // 3) xp = tanh(A0 @ W_x0^T)  [8192 x 160 x 1024]
    gemm_mma<EPI_TANH><<<dim3(2, 64), 256, SMEMSZ>>>(pA0, pWx0r, nullptr, pxp,
                                                     160, 1024, 1024, 1024, 160,
                                                     0, 0, 0, 0, nullptr);

    // 4) fused mus+lerp [8192 x 1024 x 32] x5 over z
    gemm_mma<EPI_LERP><<<dim3(8, 64, 5), 256, SMEMSZ>>>(pxp, pWx2r, x_bias, pA5,
                                                        1024, 32, 160, 160, 1024,
                                                        32, 32, 1024, ASTRIDE, x);

    // 5) merged r+k projections (z=2)
    gemm_mma<EPI_NONE><<<dim3(4, 64, 2), 256, SMEMSZ>>>(pAr, pWrk, nullptr, prk,
                                                        KD, 1024, 1024, 1024, KD,
                                                        2 * ASTRIDE, (size_t)KD * HID, 0, (size_t)MM * KD, nullptr);
    // 6) merged v+g projections (z=2)
    gemm_mma<EPI_NONE><<<dim3(8, 64, 2), 256, SMEMSZ>>>(pAv, pWvg, nullptr, pvg,
                                                        VD, 1024, 1024, 1024, VD,
                                                        ASTRIDE, (size_t)VD * HID, 0, (size_t)MM * VD, nullptr);

    // 7-9) w path (fp32): split-K w1 -> sum+tanh -> w2 decay
    sgemm_nt<EPI_NONE><<<dim3(1, 64, 4), 256>>>(pAw, W_w1, nullptr, pwt4,
                                                MM, 64, 256, 1024, 1024, 64,
                                                256, 256, MM * 64);
    tanh_sum_kernel<<<(MM * 64 + 255) / 256, 256>>>();
    sgemm_nt<EPI_DECAY><<<dim3(4, 64), 256>>>(pwt, W_w2, b_w2, pdec,
                                              MM, KD, 64, 64, 64, KD, 0, 0, 0);

    // 10-12) bonus scalar, recurrent scan, groupnorm+gate
    c_kernel<<<(MM * NH * 32 + 255) / 256, 256>>>(bonus);
    scan_kernel<<<256, 128>>>();
    gn_gate_kernel<<<MM * NH, 256>>>(gnw, gnb);

    // 13) output projection [8192 x 1024 x 1024]
    gemm_mma<EPI_NONE><<<dim3(8, 64), 256, SMEMSZ>>>(pgate, pWor, nullptr, out,
                                                     HID, 1024, 1024, 1024, HID,
                                                     0, 0, 0, 0, nullptr);
}

// round 15
// speedup vs baseline: 2.2982x; 1.0420x over previous
#include <cuda_runtime.h>
#include <cuda_bf16.h>
#include <cstdint>
#include <math.h>

// ---------------------------------------------------------------------------
// RWKV6Attention: B=4, T=2048, HID=1024, NH=4, KD=512, VD=1024, DK=128, DV=256
// Round 15: Round-14 kernels unchanged; launch DAG parallelized with a
// second (non-blocking) stream captured via fork/join events:
//   - lerp0 overlaps prep_weights
//   - w-path (w1 -> tanh_sum -> w2) overlaps rk + vg projection GEMMs
// ---------------------------------------------------------------------------

#define BB 4
#define TT 2048
#define HID 1024
#define NH 4
#define KD 512
#define VD 1024
#define DK 128
#define DV 256
#define MM (BB*TT)   // 8192

// ------------------------- scratch (device globals) ------------------------
__device__ float g_A0  [(size_t)MM*HID];
__device__ float g_xp  [(size_t)MM*160];
__device__ float g_A5  [(size_t)5*MM*HID];   // slot-major: r,w,k,v,g
__device__ float g_rk  [(size_t)2*MM*KD];    // slot 0: r, slot 1: k
__device__ float g_dec [(size_t)MM*KD];
__device__ float g_wt4 [(size_t)4*MM*64];
__device__ float g_wt  [(size_t)MM*64];
__device__ float g_vg  [(size_t)2*MM*VD];    // slot 0: v, slot 1: g
__device__ float g_c   [(size_t)BB*NH*TT];
__device__ float g_o   [(size_t)MM*VD];
__device__ float g_gate[(size_t)MM*VD];

// tf32-rounded weights
__device__ float g_Wx0r[160*HID];
__device__ float g_Wrk [(size_t)2*KD*HID];
__device__ float g_Wvg [(size_t)2*VD*HID];
__device__ float g_Wor [HID*VD];
__device__ float g_Wx2r[HID*160];

// ------------------------- helpers -----------------------------------------
__device__ __forceinline__ uint32_t smem_u32(const void* p) {
    uint32_t a;
    asm("{ .reg .u64 t; cvta.to.shared.u64 t, %1; cvt.u32.u64 %0, t; }" : "=r"(a) : "l"(p));
    return a;
}
__device__ __forceinline__ float tf32r(float x) {
    uint32_t u;
    asm("cvt.rna.tf32.f32 %0, %1;" : "=r"(u) : "f"(x));
    return __uint_as_float(u);
}
__device__ __forceinline__ void cp16(uint32_t dst, const void* src, bool pred) {
    asm volatile("cp.async.ca.shared.global [%0], [%1], 16, %2;"
                 :: "r"(dst), "l"(src), "r"(pred ? 16u : 0u));
}
__device__ __forceinline__ void mma1688(float* c, const uint32_t* a, const uint32_t* b) {
    asm volatile(
        "mma.sync.aligned.m16n8k8.row.col.f32.tf32.tf32.f32 "
        "{%0,%1,%2,%3}, {%4,%5,%6,%7}, {%8,%9}, {%0,%1,%2,%3};"
        : "+f"(c[0]), "+f"(c[1]), "+f"(c[2]), "+f"(c[3])
        : "r"(a[0]), "r"(a[1]), "r"(a[2]), "r"(a[3]), "r"(b[0]), "r"(b[1]));
}

// ------------------------- tf32 mma.sync GEMM -------------------------------
enum { EPI_NONE = 0, EPI_TANH = 1, EPI_DECAY = 2, EPI_LERP = 3 };

#define SMPAD 36
#define SMBUF (128*SMPAD)

template <int EPI>
__global__ void __launch_bounds__(256) gemm_mma(
    const float* __restrict__ A, const float* __restrict__ W,
    const float* __restrict__ bias, float* __restrict__ C,
    int N, int K, int lda, int ldw, int ldc,
    size_t zsA, size_t zsW, size_t zsB, size_t zsC,
    const float* __restrict__ X)
{
    extern __shared__ float sm[];
    float* sA = sm;                    // [2][SMBUF]
    float* sB = sm + 2 * SMBUF;        // [2][SMBUF]

    const int z = blockIdx.z;
    A += (size_t)z * zsA;
    W += (size_t)z * zsW;
    if (bias) bias += (size_t)z * zsB;
    C += (size_t)z * zsC;

    const int tid = threadIdx.x;
    const int lane = tid & 31;
    const int wid = tid >> 5;
    const int bm = blockIdx.y * 128;
    const int bn = blockIdx.x * 128;
    const int wm = (wid >> 2) * 64;
    const int wn = (wid & 3) * 32;
    const int grp = lane >> 2;
    const int tg = lane & 3;

    float acc[4][4][4];
#pragma unroll
    for (int i = 0; i < 4; i++)
#pragma unroll
        for (int j = 0; j < 4; j++)
#pragma unroll
            for (int q = 0; q < 4; q++) acc[i][j][q] = 0.f;

    auto load_tiles = [&](int ks, int buf) {
#pragma unroll
        for (int i = 0; i < 4; i++) {
            int idx = i * 256 + tid;
            int row = idx >> 3, c4 = idx & 7;
            const float* srcA = A + (size_t)(bm + row) * lda + ks * 32 + c4 * 4;
            cp16(smem_u32(sA + buf * SMBUF + row * SMPAD + c4 * 4), srcA, true);
            int gn = bn + row;
            bool ok = gn < N;
            const float* srcB = W + (size_t)(ok ? gn : 0) * ldw + ks * 32 + c4 * 4;
            cp16(smem_u32(sB + buf * SMBUF + row * SMPAD + c4 * 4), srcB, ok);
        }
        asm volatile("cp.async.commit_group;" ::: "memory");
    };

    const int S = K >> 5;
    load_tiles(0, 0);

    for (int s = 0; s < S; s++) {
        const int buf = s & 1;
        if (s + 1 < S) {
            load_tiles(s + 1, buf ^ 1);
            asm volatile("cp.async.wait_group 1;" ::: "memory");
        } else {
            asm volatile("cp.async.wait_group 0;" ::: "memory");
        }
        __syncthreads();

        const float* pA = sA + buf * SMBUF + wm * SMPAD;
        const float* pB = sB + buf * SMBUF + wn * SMPAD;
#pragma unroll
        for (int kk = 0; kk < 4; kk++) {
            const int kb = kk * 8;
            uint32_t a[4][4], b[4][2];
#pragma unroll
            for (int mt = 0; mt < 4; mt++) {
                int r0 = mt * 16 + grp;
                a[mt][0] = __float_as_uint(pA[r0 * SMPAD + kb + tg]);
                a[mt][1] = __float_as_uint(pA[(r0 + 8) * SMPAD + kb + tg]);
                a[mt][2] = __float_as_uint(pA[r0 * SMPAD + kb + tg + 4]);
                a[mt][3] = __float_as_uint(pA[(r0 + 8) * SMPAD + kb + tg + 4]);
            }
#pragma unroll
            for (int nt = 0; nt < 4; nt++) {
                int c0 = nt * 8 + grp;
                b[nt][0] = __float_as_uint(pB[c0 * SMPAD + kb + tg]);
                b[nt][1] = __float_as_uint(pB[c0 * SMPAD + kb + tg + 4]);
            }
#pragma unroll
            for (int mt = 0; mt < 4; mt++)
#pragma unroll
                for (int nt = 0; nt < 4; nt++)
                    mma1688(acc[mt][nt], a[mt], b[nt]);
        }
        __syncthreads();
    }

    // epilogue
#pragma unroll
    for (int mt = 0; mt < 4; mt++) {
#pragma unroll
        for (int nt = 0; nt < 4; nt++) {
            int col = bn + wn + nt * 8 + tg * 2;
            if (col >= N) continue;
            float bv0 = bias ? bias[col] : 0.f;
            float bv1 = bias ? bias[col + 1] : 0.f;
#pragma unroll
            for (int half = 0; half < 2; half++) {
                int row = bm + wm + mt * 16 + grp + half * 8;
                float v0 = acc[mt][nt][half * 2 + 0] + bv0;
                float v1 = acc[mt][nt][half * 2 + 1] + bv1;
                if (EPI == EPI_TANH)  { v0 = tf32r(tanhf(v0)); v1 = tf32r(tanhf(v1)); }
                if (EPI == EPI_DECAY) { v0 = expf(-expf(v0)); v1 = expf(-expf(v1)); }
                if (EPI == EPI_LERP) {
                    size_t xi = (size_t)row * HID + col;
                    float2 xv = *(const float2*)&X[xi];
                    int t = row & (TT - 1);
                    float2 sh = (t == 0) ? make_float2(0.f, 0.f)
                                         : *(const float2*)&X[xi - HID];
                    v0 = xv.x + (sh.x - xv.x) * v0;
                    v1 = xv.y + (sh.y - xv.y) * v1;
                    if (z != 1) { v0 = tf32r(v0); v1 = tf32r(v1); }  // w slot stays fp32
                }
                *(float2*)&C[(size_t)row * ldc + col] = make_float2(v0, v1);
            }
        }
    }
}

// ------------------------- fp32 SGEMM (w path) ------------------------------
template <int EPI>
__global__ void sgemm_nt(const float* __restrict__ A, const float* __restrict__ W,
                         const float* __restrict__ bias, float* __restrict__ C,
                         int M, int N, int K, int lda, int ldw, int ldc,
                         int zsA, int zsW, int zsC) {
    __shared__ float As[8][128];
    __shared__ float Ws[8][128];
    const int z = blockIdx.z;
    A += (size_t)z * zsA;
    W += (size_t)z * zsW;
    C += (size_t)z * zsC;

    const int tid = threadIdx.x;
    const int bm = blockIdx.y * 128;
    const int bn = blockIdx.x * 128;
    const int lr = tid >> 1;
    const int lc = (tid & 1) << 2;
    const int tx = tid & 15;
    const int ty = tid >> 4;

    float acc[8][8];
#pragma unroll
    for (int i = 0; i < 8; i++)
#pragma unroll
        for (int j = 0; j < 8; j++) acc[i][j] = 0.f;

    const bool wok = (bn + lr) < N;
    const float* Aptr = A + (size_t)(bm + lr) * lda + lc;
    const float* Wptr = W + (size_t)(wok ? (bn + lr) : 0) * ldw + lc;

    for (int k0 = 0; k0 < K; k0 += 8) {
        float4 av = *(const float4*)(Aptr + k0);
        float4 wv = wok ? *(const float4*)(Wptr + k0) : make_float4(0.f, 0.f, 0.f, 0.f);
        As[lc + 0][lr] = av.x; As[lc + 1][lr] = av.y; As[lc + 2][lr] = av.z; As[lc + 3][lr] = av.w;
        Ws[lc + 0][lr] = wv.x; Ws[lc + 1][lr] = wv.y; Ws[lc + 2][lr] = wv.z; Ws[lc + 3][lr] = wv.w;
        __syncthreads();
#pragma unroll
        for (int kk = 0; kk < 8; kk++) {
            float a[8], b[8];
            *(float4*)&a[0] = *(const float4*)&As[kk][ty * 8];
            *(float4*)&a[4] = *(const float4*)&As[kk][ty * 8 + 4];
            *(float4*)&b[0] = *(const float4*)&Ws[kk][tx * 8];
            *(float4*)&b[4] = *(const float4*)&Ws[kk][tx * 8 + 4];
#pragma unroll
            for (int i = 0; i < 8; i++)
#pragma unroll
                for (int j = 0; j < 8; j++) acc[i][j] = fmaf(a[i], b[j], acc[i][j]);
        }
        __syncthreads();
    }

#pragma unroll
    for (int i = 0; i < 8; i++) {
        int row = bm + ty * 8 + i;
#pragma unroll
        for (int j = 0; j < 8; j++) {
            int col = bn + tx * 8 + j;
            if (col < N) {
                float val = acc[i][j];
                if (bias) val += bias[col];
                if (EPI == EPI_TANH)  val = tanhf(val);
                if (EPI == EPI_DECAY) val = expf(-expf(val));
                C[(size_t)row * ldc + col] = val;
            }
        }
    }
}

__global__ void tanh_sum_kernel() {
    int i = blockIdx.x * 256 + threadIdx.x;
    if (i >= MM * 64) return;
    float s = g_wt4[i] + g_wt4[i + MM * 64] + g_wt4[i + 2 * MM * 64] + g_wt4[i + 3 * MM * 64];
    g_wt[i] = tanhf(s);
}

// ------------------------- merged weight prep -------------------------------
#define PN0 (160*HID)
#define PN1 (KD*HID)
#define PN2 (KD*HID)
#define PN3 (VD*HID)
#define PN4 (VD*HID)
#define PN5 (HID*VD)
#define PN6 (HID*160)
#define PTOT (PN0+PN1+PN2+PN3+PN4+PN5+PN6)

__global__ void prep_weights(const float* __restrict__ Wx0, const float* __restrict__ Wr,
                             const float* __restrict__ Wk, const float* __restrict__ Wv,
                             const float* __restrict__ Wg, const float* __restrict__ Wo,
                             const float* __restrict__ Wx2) {
    int i = blockIdx.x * 256 + threadIdx.x;
    if (i >= PTOT) return;
    if (i < PN0) { g_Wx0r[i] = tf32r(Wx0[i]); return; }
    i -= PN0;
    if (i < PN1) { g_Wrk[i] = tf32r(Wr[i]); return; }
    i -= PN1;
    if (i < PN2) { g_Wrk[(size_t)KD * HID + i] = tf32r(Wk[i]); return; }
    i -= PN2;
    if (i < PN3) { g_Wvg[i] = tf32r(Wv[i]); return; }
    i -= PN3;
    if (i < PN4) { g_Wvg[(size_t)VD * HID + i] = tf32r(Wg[i]); return; }
    i -= PN4;
    if (i < PN5) { g_Wor[i] = tf32r(Wo[i]); return; }
    i -= PN5;
    g_Wx2r[i] = tf32r(Wx2[i]);
}

// ------------------------- elementwise kernels ------------------------------
__global__ void lerp0_kernel(const float* __restrict__ x, const float* __restrict__ mu0) {
    size_t i = (size_t)blockIdx.x * 256 + threadIdx.x;
    if (i >= (size_t)MM * HID) return;
    int h = (int)(i & (HID - 1));
    size_t bt = i >> 10;
    int t = (int)(bt & (TT - 1));
    float xv = x[i];
    float sh = (t == 0) ? 0.f : x[i - HID];
    g_A0[i] = tf32r(xv + (sh - xv) * mu0[h]);
}

__global__ void c_kernel(const float* __restrict__ bonus) {
    int w = (blockIdx.x * blockDim.x + threadIdx.x) >> 5;
    int lane = threadIdx.x & 31;
    if (w >= MM * NH) return;
    int h = w & (NH - 1);
    size_t bt = (size_t)w >> 2;
    const float* rp = g_rk + bt * KD + h * DK;
    const float* kp = g_rk + (size_t)MM * KD + bt * KD + h * DK;
    const float* up = bonus + h * DK;
    float s = 0.f;
#pragma unroll
    for (int i = lane; i < DK; i += 32) s += rp[i] * up[i] * kp[i];
#pragma unroll
    for (int off = 16; off; off >>= 1) s += __shfl_xor_sync(0xffffffffu, s, off);
    if (lane == 0) {
        int b = (int)(bt / TT), t = (int)(bt % TT);
        g_c[(size_t)(b * NH + h) * TT + t] = s;
    }
}

// ------------------------- RWKV6 recurrent scan (R14) -----------------------
#define SCH 8

__global__ void __launch_bounds__(128) scan_kernel() {
    const int pair = blockIdx.x >> 4;
    const int chunk16 = blockIdx.x & 15;
    const int b = pair >> 2;
    const int h = pair & 3;
    const int col0 = chunk16 * 16;
    const int tid = threadIdx.x;
    const int kg = tid >> 4;         // 0..7
    const int col = tid & 15;        // 0..15

    __shared__ __align__(16) float sr_c[2][SCH * 128];
    __shared__ __align__(16) float se_c[2][SCH * 128];
    __shared__ __align__(16) float sk_c[2][SCH * 128];
    __shared__ __align__(16) float sv_c[2][SCH * 16];
    __shared__ __align__(16) float sc_c[2][SCH];
    __shared__ float pbuf[SCH][8][16];

    float S[16];
#pragma unroll
    for (int i = 0; i < 16; i++) S[i] = 0.f;

    const float* cb = g_c + (size_t)pair * TT;
    const float* rsrc = g_rk;
    const float* ksrc = g_rk + (size_t)MM * KD;
    const size_t rkbase = (size_t)(b * TT) * KD + h * DK;
    const size_t vbase  = (size_t)(b * TT) * VD + h * DV + col0;

    auto load_chunk = [&](int c, int buf) {
        const int t0 = c * SCH;
#pragma unroll
        for (int i = 0; i < 2; i++) {
            int idx = i * 128 + tid;
            int row = idx >> 5;
            int c4  = (idx & 31) * 4;
            size_t g = rkbase + (size_t)(t0 + row) * KD + c4;
            cp16(smem_u32(&sr_c[buf][row * 128 + c4]), rsrc  + g, true);
            cp16(smem_u32(&se_c[buf][row * 128 + c4]), g_dec + g, true);
            cp16(smem_u32(&sk_c[buf][row * 128 + c4]), ksrc  + g, true);
        }
        if (tid < 32) {
            int row = tid >> 2;
            int c4 = (tid & 3) * 4;
            cp16(smem_u32(&sv_c[buf][row * 16 + c4]),
                 g_vg + vbase + (size_t)(t0 + row) * VD + c4, true);
        }
        if (tid < 2) {
            cp16(smem_u32(&sc_c[buf][tid * 4]), cb + t0 + tid * 4, true);
        }
        asm volatile("cp.async.commit_group;" ::: "memory");
    };

    load_chunk(0, 0);
    const int NC = TT / SCH;

    for (int c = 0; c < NC; c++) {
        const int p = c & 1;
        if (c + 1 < NC) {
            load_chunk(c + 1, p ^ 1);
            asm volatile("cp.async.wait_group 1;" ::: "memory");
        } else {
            asm volatile("cp.async.wait_group 0;" ::: "memory");
        }
        __syncthreads();

#pragma unroll
        for (int tt = 0; tt < SCH; tt++) {
            const float vj = sv_c[p][tt * 16 + col];
            const int kb = tt * 128 + kg * 16;
            float op0 = 0.f, op1 = 0.f, op2 = 0.f, op3 = 0.f;
            {
                float4 r4 = *(const float4*)&sr_c[p][kb + 0];
                float4 e4 = *(const float4*)&se_c[p][kb + 0];
                float4 k4 = *(const float4*)&sk_c[p][kb + 0];
                op0 = fmaf(r4.x, S[0], op0); S[0] = fmaf(e4.x, S[0], k4.x * vj);
                op0 = fmaf(r4.y, S[1], op0); S[1] = fmaf(e4.y, S[1], k4.y * vj);
                op0 = fmaf(r4.z, S[2], op0); S[2] = fmaf(e4.z, S[2], k4.z * vj);
                op0 = fmaf(r4.w, S[3], op0); S[3] = fmaf(e4.w, S[3], k4.w * vj);
            }
            {
                float4 r4 = *(const float4*)&sr_c[p][kb + 4];
                float4 e4 = *(const float4*)&se_c[p][kb + 4];
                float4 k4 = *(const float4*)&sk_c[p][kb + 4];
                op1 = fmaf(r4.x, S[4], op1); S[4] = fmaf(e4.x, S[4], k4.x * vj);
                op1 = fmaf(r4.y, S[5], op1); S[5] = fmaf(e4.y, S[5], k4.y * vj);
                op1 = fmaf(r4.z, S[6], op1); S[6] = fmaf(e4.z, S[6], k4.z * vj);
                op1 = fmaf(r4.w, S[7], op1); S[7] = fmaf(e4.w, S[7], k4.w * vj);
            }
            {
                float4 r4 = *(const float4*)&sr_c[p][kb + 8];
                float4 e4 = *(const float4*)&se_c[p][kb + 8];
                float4 k4 = *(const float4*)&sk_c[p][kb + 8];
                op2 = fmaf(r4.x, S[8], op2);  S[8]  = fmaf(e4.x, S[8],  k4.x * vj);
                op2 = fmaf(r4.y, S[9], op2);  S[9]  = fmaf(e4.y, S[9],  k4.y * vj);
                op2 = fmaf(r4.z, S[10], op2); S[10] = fmaf(e4.z, S[10], k4.z * vj);
                op2 = fmaf(r4.w, S[11], op2); S[11] = fmaf(e4.w, S[11], k4.w * vj);
            }
            {
                float4 r4 = *(const float4*)&sr_c[p][kb + 12];
                float4 e4 = *(const float4*)&se_c[p][kb + 12];
                float4 k4 = *(const float4*)&sk_c[p][kb + 12];
                op3 = fmaf(r4.x, S[12], op3); S[12] = fmaf(e4.x, S[12], k4.x * vj);
                op3 = fmaf(r4.y, S[13], op3); S[13] = fmaf(e4.y, S[13], k4.y * vj);
                op3 = fmaf(r4.z, S[14], op3); S[14] = fmaf(e4.z, S[14], k4.z * vj);
                op3 = fmaf(r4.w, S[15], op3); S[15] = fmaf(e4.w, S[15], k4.w * vj);
            }
            pbuf[tt][kg][col] = (op0 + op1) + (op2 + op3);
        }
        __syncthreads();

        {
            const int tt = tid >> 4;
            const int jc = tid & 15;
            float o = pbuf[tt][0][jc] + pbuf[tt][1][jc] + pbuf[tt][2][jc] + pbuf[tt][3][jc]
                    + pbuf[tt][4][jc] + pbuf[tt][5][jc] + pbuf[tt][6][jc] + pbuf[tt][7][jc]
                    + sv_c[p][tt * 16 + jc] * sc_c[p][tt];
            g_o[vbase + (size_t)(c * SCH + tt) * VD + jc] = o;
        }
        __syncthreads();
    }
}

// ------------------------- GroupNorm + swish gate ---------------------------
__global__ void gn_gate_kernel(const float* __restrict__ gnw, const float* __restrict__ gnb) {
    size_t bt = (size_t)(blockIdx.x >> 2);
    int h = blockIdx.x & 3;
    int j = threadIdx.x;
    size_t idx = bt * VD + h * DV + j;
    float val = g_o[idx];

    __shared__ float ssum[8], ssq[8];
    float s = val, q = val * val;
#pragma unroll
    for (int off = 16; off; off >>= 1) {
        s += __shfl_xor_sync(0xffffffffu, s, off);
        q += __shfl_xor_sync(0xffffffffu, q, off);
    }
    int wid = threadIdx.x >> 5, lane = threadIdx.x & 31;
    if (lane == 0) { ssum[wid] = s; ssq[wid] = q; }
    __syncthreads();
    if (threadIdx.x == 0) {
        float ts = 0.f, tq = 0.f;
#pragma unroll
        for (int i = 0; i < 8; i++) { ts += ssum[i]; tq += ssq[i]; }
        ssum[0] = ts; ssq[0] = tq;
    }
    __syncthreads();
    float mean = ssum[0] * (1.f / DV);
    float var = ssq[0] * (1.f / DV) - mean * mean;
    float ny = (val - mean) * rsqrtf(var + 1e-5f) * gnw[h * DV + j] + gnb[h * DV + j];
    float gv = g_vg[(size_t)MM * VD + idx];
    float sig = 1.f / (1.f + expf(-gv));
    g_gate[idx] = tf32r(ny * gv * sig);
}

// ------------------------- launch ------------------------------------------
extern "C" void kernel_launch(void* const* d_in, const int* in_sizes, int n_in,
                              void* d_out, int out_size) {
    const float* x      = (const float*)d_in[0];
    const float* mu0    = (const float*)d_in[1];
    const float* W_x0   = (const float*)d_in[2];
    const float* W_x2   = (const float*)d_in[3];
    const float* x_bias = (const float*)d_in[4];
    const float* W_r    = (const float*)d_in[5];
    const float* W_w1   = (const float*)d_in[6];
    const float* W_w2   = (const float*)d_in[7];
    const float* b_w2   = (const float*)d_in[8];
    const float* W_k    = (const float*)d_in[9];
    const float* W_v    = (const float*)d_in[10];
    const float* W_g    = (const float*)d_in[11];
    const float* bonus  = (const float*)d_in[12];
    const float* gnw    = (const float*)d_in[13];
    const float* gnb    = (const float*)d_in[14];
    const float* W_o    = (const float*)d_in[15];
    float* out = (float*)d_out;

    float *pA0, *pxp, *pA5, *prk, *pdec, *pwt4, *pwt, *pvg, *pgate;
    float *pWx0r, *pWrk, *pWvg, *pWor, *pWx2r;
    cudaGetSymbolAddress((void**)&pA0, g_A0);
    cudaGetSymbolAddress((void**)&pxp, g_xp);
    cudaGetSymbolAddress((void**)&pA5, g_A5);
    cudaGetSymbolAddress((void**)&prk, g_rk);
    cudaGetSymbolAddress((void**)&pdec, g_dec);
    cudaGetSymbolAddress((void**)&pwt4, g_wt4);
    cudaGetSymbolAddress((void**)&pwt, g_wt);
    cudaGetSymbolAddress((void**)&pvg, g_vg);
    cudaGetSymbolAddress((void**)&pgate, g_gate);
    cudaGetSymbolAddress((void**)&pWx0r, g_Wx0r);
    cudaGetSymbolAddress((void**)&pWrk, g_Wrk);
    cudaGetSymbolAddress((void**)&pWvg, g_Wvg);
    cudaGetSymbolAddress((void**)&pWor, g_Wor);
    cudaGetSymbolAddress((void**)&pWx2r, g_Wx2r);

    const size_t ASTRIDE = (size_t)MM * HID;
    float* pAr = pA5 + 0 * ASTRIDE;
    float* pAw = pA5 + 1 * ASTRIDE;
    float* pAv = pA5 + 3 * ASTRIDE;

    const int SMEMSZ = 4 * SMBUF * (int)sizeof(float);  // 73728
    cudaFuncSetAttribute(gemm_mma<EPI_NONE>, cudaFuncAttributeMaxDynamicSharedMemorySize, SMEMSZ);
    cudaFuncSetAttribute(gemm_mma<EPI_TANH>, cudaFuncAttributeMaxDynamicSharedMemorySize, SMEMSZ);
    cudaFuncSetAttribute(gemm_mma<EPI_LERP>, cudaFuncAttributeMaxDynamicSharedMemorySize, SMEMSZ);

    // One-time stream/event setup (first call happens OUTSIDE graph capture:
    // the harness runs a correctness call before capturing). Handles persist;
    // every call enqueues the identical fork/join DAG.
    static cudaStream_t s1 = nullptr;
    static cudaEvent_t ev1 = nullptr, ev2 = nullptr, ev3 = nullptr, ev4 = nullptr;
    if (s1 == nullptr) {
        cudaStreamCreateWithFlags(&s1, cudaStreamNonBlocking);
        cudaEventCreateWithFlags(&ev1, cudaEventDisableTiming);
        cudaEventCreateWithFlags(&ev2, cudaEventDisableTiming);
        cudaEventCreateWithFlags(&ev3, cudaEventDisableTiming);
        cudaEventCreateWithFlags(&ev4, cudaEventDisableTiming);
    }

    const int EW_BLOCKS = (MM * HID + 255) / 256;

    // ---- fork A: lerp0 on s1, prep on main -------------------------------
    cudaEventRecord(ev1, 0);
    cudaStreamWaitEvent(s1, ev1, 0);
    lerp0_kernel<<<EW_BLOCKS, 256, 0, s1>>>(x, mu0);
    cudaEventRecord(ev2, s1);

    prep_weights<<<(PTOT + 255) / 256, 256>>>(W_x0, W_r, W_k, W_v, W_g, W_o, W_x2);
    cudaStreamWaitEvent(0, ev2, 0);                       // join lerp0

    // ---- main chain: xp, mus+lerp ----------------------------------------
    gemm_mma<EPI_TANH><<<dim3(2, 64), 256, SMEMSZ>>>(pA0, pWx0r, nullptr, pxp,
                                                     160, 1024, 1024, 1024, 160,
                                                     0, 0, 0, 0, nullptr);
    gemm_mma<EPI_LERP><<<dim3(8, 64, 5), 256, SMEMSZ>>>(pxp, pWx2r, x_bias, pA5,
                                                        1024, 32, 160, 160, 1024,
                                                        32, 32, 1024, ASTRIDE, x);

    // ---- fork B: w-path on s1, projections on main -----------------------
    cudaEventRecord(ev3, 0);
    cudaStreamWaitEvent(s1, ev3, 0);
    sgemm_nt<EPI_NONE><<<dim3(1, 64, 4), 256, 0, s1>>>(pAw, W_w1, nullptr, pwt4,
                                                       MM, 64, 256, 1024, 1024, 64,
                                                       256, 256, MM * 64);
    tanh_sum_kernel<<<(MM * 64 + 255) / 256, 256, 0, s1>>>();
    sgemm_nt<EPI_DECAY><<<dim3(4, 64), 256, 0, s1>>>(pwt, W_w2, b_w2, pdec,
                                                     MM, KD, 64, 64, 64, KD, 0, 0, 0);
    cudaEventRecord(ev4, s1);

    gemm_mma<EPI_NONE><<<dim3(4, 64, 2), 256, SMEMSZ>>>(pAr, pWrk, nullptr, prk,
                                                        KD, 1024, 1024, 1024, KD,
                                                        2 * ASTRIDE, (size_t)KD * HID, 0, (size_t)MM * KD, nullptr);
    c_kernel<<<(MM * NH * 32 + 255) / 256, 256>>>(bonus);
    gemm_mma<EPI_NONE><<<dim3(8, 64, 2), 256, SMEMSZ>>>(pAv, pWvg, nullptr, pvg,
                                                        VD, 1024, 1024, 1024, VD,
                                                        ASTRIDE, (size_t)VD * HID, 0, (size_t)MM * VD, nullptr);
    cudaStreamWaitEvent(0, ev4, 0);                       // join w-path before scan

    // ---- tail: scan, gn+gate, out GEMM -----------------------------------
    scan_kernel<<<256, 128>>>();
    gn_gate_kernel<<<MM * NH, 256>>>(gnw, gnb);
    gemm_mma<EPI_NONE><<<dim3(8, 64), 256, SMEMSZ>>>(pgate, pWor, nullptr, out,
                                                     HID, 1024, 1024, 1024, HID,
                                                     0, 0, 0, 0, nullptr);
}